// round 13
// baseline (speedup 1.0000x reference)
#include <cuda_runtime.h>
#include <cuda_fp16.h>
#include <math.h>

#define EMB    64
#define NHEAD  4
#define HEADD  16
#define BB     8
#define SS     2048
#define NTOK   (BB*SS)            // 16384
#define EPS    1e-5f
// exp2-domain scale: 1/sqrt(16) * log2(e)
#define QSCALE (0.25f * 1.44269504088896f)

#define BK     64                 // keys per chunk
#define NCH    (SS/BK)            // 32

// ---------------- device scratch (no allocations allowed) ----------------
__device__ __align__(16) __half g_Qh[NTOK*EMB];   // [bh][s][16], QSCALE folded in
__device__ __align__(16) __half g_Kh[NTOK*EMB];   // [bh][s][16]
__device__ __align__(16) __half g_Vt[NTOK*EMB];   // [bh][16][s]  (transposed!)
__device__ __align__(16) float  g_heads[NTOK*EMB];  // concat layout [b][s][h*16+k]
__device__ __align__(16) __half g_Wth[192*72];    // QKV weights [n][k]
__device__ __align__(16) __half g_Wpost[3*64*72]; // Wo|W1|W2 [n][k]

__device__ __forceinline__ void mma_16816(float* d, const unsigned* a,
                                          unsigned b0, unsigned b1) {
    asm volatile(
        "mma.sync.aligned.m16n8k16.row.col.f32.f16.f16.f32 "
        "{%0,%1,%2,%3}, {%4,%5,%6,%7}, {%8,%9}, {%0,%1,%2,%3};\n"
        : "+f"(d[0]), "+f"(d[1]), "+f"(d[2]), "+f"(d[3])
        : "r"(a[0]), "r"(a[1]), "r"(a[2]), "r"(a[3]), "r"(b0), "r"(b1));
}

__device__ __forceinline__ unsigned packh2(float x, float y) {
    __half2 h = __floats2half2_rn(x, y);
    return *(unsigned*)&h;
}

// single-instruction packed fp16 exp2 (forces MUFU.EX2 on f16x2, no unpack)
__device__ __forceinline__ unsigned h2exp2_fast(unsigned x) {
    unsigned r;
    asm("ex2.approx.f16x2 %0, %1;" : "=r"(r) : "r"(x));
    return r;
}

// =====================================================================
// Kernel 0: one-time weight conversion to fp16 B-fragment layouts.
// =====================================================================
__global__ void prep_kernel(const float* __restrict__ Wq,
                            const float* __restrict__ Wk,
                            const float* __restrict__ Wv,
                            const float* __restrict__ Wo,
                            const float* __restrict__ W1,
                            const float* __restrict__ W2)
{
    const int i = blockIdx.x * 256 + threadIdx.x;
    if (i < 192 * 64) {
        const int n = i % 192, k = i / 192;
        float w;
        if (n < 64)        w = Wq[(n >> 4) * 1024 + k * 16 + (n & 15)] * QSCALE;
        else if (n < 128)  w = Wk[((n - 64) >> 4) * 1024 + k * 16 + ((n - 64) & 15)];
        else               w = Wv[((n - 128) >> 4) * 1024 + k * 16 + ((n - 128) & 15)];
        g_Wth[n * 72 + k] = __float2half_rn(w);
    } else if (i < 192 * 64 + 3 * 64 * 64) {
        const int j = i - 192 * 64;
        const int m = j >> 12;          // 0 Wo, 1 W1, 2 W2
        const int r = j & 4095;
        const int n = r & 63, k = r >> 6;
        const float* W = (m == 0) ? Wo : (m == 1) ? W1 : W2;
        g_Wpost[(m * 64 + n) * 72 + k] = __float2half_rn(W[k * 64 + n]);
    }
}

// =====================================================================
// Kernel 1: QKV projection on tensor cores. B-frags direct from L1/L2.
// =====================================================================
__global__ void __launch_bounds__(128) qkv_kernel(const float* __restrict__ data)
{
    __shared__ __align__(16) __half stage_v[64 * 66]; // 8448 B

    const int tid  = threadIdx.x;
    const int warp = tid >> 5;
    const int lane = tid & 31;
    const int gr   = lane >> 2;
    const int gc   = lane & 3;

    const int tile = blockIdx.x * 4 + warp;
    const int tok0 = tile * 16;

    unsigned a[4][4];
#pragma unroll
    for (int kt = 0; kt < 4; kt++) {
        const float* r0 = data + (size_t)(tok0 + gr) * 64 + kt * 16 + 2 * gc;
        const float* r8 = r0 + 8 * 64;
        float2 x0 = *(const float2*)r0;
        float2 x8 = *(const float2*)r8;
        float2 y0 = *(const float2*)(r0 + 8);
        float2 y8 = *(const float2*)(r8 + 8);
        a[kt][0] = packh2(x0.x, x0.y); a[kt][1] = packh2(x8.x, x8.y);
        a[kt][2] = packh2(y0.x, y0.y); a[kt][3] = packh2(y8.x, y8.y);
    }

    float acc[24][4] = {};
#pragma unroll
    for (int nt = 0; nt < 24; nt++) {
#pragma unroll
        for (int kt = 0; kt < 4; kt++) {
            const __half* base = &g_Wth[(nt * 8 + gr) * 72 + kt * 16 + 2 * gc];
            unsigned b0 = *(const unsigned*)base;
            unsigned b1 = *(const unsigned*)(base + 8);
            mma_16816(acc[nt], a[kt], b0, b1);
        }
    }

#pragma unroll
    for (int nt = 0; nt < 8; nt++) {
        const int vcol = nt * 8 + 2 * gc;
        *(__half2*)&stage_v[(warp * 16 + gr)     * 66 + vcol] =
            __floats2half2_rn(acc[16 + nt][0], acc[16 + nt][1]);
        *(__half2*)&stage_v[(warp * 16 + gr + 8) * 66 + vcol] =
            __floats2half2_rn(acc[16 + nt][2], acc[16 + nt][3]);
    }
    __syncthreads();

    const int b  = tok0 >> 11;
    const int sb = tok0 & 2047;
#pragma unroll
    for (int nt = 0; nt < 8; nt++) {           // Q
        const int head = nt >> 1;
        const int kk0  = (nt & 1) * 8 + 2 * gc;
        const size_t base = (size_t)(b * 4 + head) * 2048;
        *(__half2*)&g_Qh[(base + sb + gr)     * 16 + kk0] = __floats2half2_rn(acc[nt][0], acc[nt][1]);
        *(__half2*)&g_Qh[(base + sb + gr + 8) * 16 + kk0] = __floats2half2_rn(acc[nt][2], acc[nt][3]);
    }
#pragma unroll
    for (int nt = 0; nt < 8; nt++) {           // K
        const int head = nt >> 1;
        const int kk0  = (nt & 1) * 8 + 2 * gc;
        const size_t base = (size_t)(b * 4 + head) * 2048;
        *(__half2*)&g_Kh[(base + sb + gr)     * 16 + kk0] = __floats2half2_rn(acc[8 + nt][0], acc[8 + nt][1]);
        *(__half2*)&g_Kh[(base + sb + gr + 8) * 16 + kk0] = __floats2half2_rn(acc[8 + nt][2], acc[8 + nt][3]);
    }

    const int s0 = (blockIdx.x * 64) & 2047;
    const int bb = (blockIdx.x * 64) >> 11;
#pragma unroll
    for (int q = 0; q < 4; q++) {
        const int idx = q * 128 + tid;
        const int c   = idx >> 3;
        const int j   = idx & 7;
        const int h   = c >> 4;
        const int kk  = c & 15;
        __half2 p0 = __halves2half2(stage_v[(8*j+0)*66+c], stage_v[(8*j+1)*66+c]);
        __half2 p1 = __halves2half2(stage_v[(8*j+2)*66+c], stage_v[(8*j+3)*66+c]);
        __half2 p2 = __halves2half2(stage_v[(8*j+4)*66+c], stage_v[(8*j+5)*66+c]);
        __half2 p3 = __halves2half2(stage_v[(8*j+6)*66+c], stage_v[(8*j+7)*66+c]);
        uint4 u;
        u.x = *(unsigned*)&p0; u.y = *(unsigned*)&p1;
        u.z = *(unsigned*)&p2; u.w = *(unsigned*)&p3;
        *(uint4*)&g_Vt[((size_t)(bb * 4 + h) * 16 + kk) * 2048 + s0 + 8 * j] = u;
    }
}

// =====================================================================
// Kernel 2: fp16 tensor-core flash attention (no-max softmax).
// 8 warps / 256 q-rows per block; K/V smem double-buffered, loads split
// K(threads 0-127) / V(threads 128-255). exp2 via single ex2.approx.f16x2.
// l via ones-column MMA (R9 shape).
// =====================================================================
__global__ void __launch_bounds__(256) attn_kernel()
{
    __shared__ __align__(16) __half Ksh[2][BK][24];   // stride 24 halves
    __shared__ __align__(16) __half Vts[2][24][72];   // [dim(+l cols)][key]

    const int bh   = blockIdx.x;
    const int tid  = threadIdx.x;
    const int warp = tid >> 5;
    const int lane = tid & 31;
    const int gr   = lane >> 2;
    const int gc   = lane & 3;
    const int qrow0 = blockIdx.y * 256 + warp * 32;

    // constant rows 16..23 of Vt tiles: dim16 = ones (row-sum column), rest 0
    for (int i = tid; i < 2 * 8 * 72; i += 256) {
        int bufi = i / (8 * 72);
        int rem  = i % (8 * 72);
        int r = rem / 72, cc = rem % 72;
        Vts[bufi][16 + r][cc] = __float2half(r == 0 ? 1.0f : 0.0f);
    }

    // Q fragments (held for whole kernel)
    const __half* Qbh = g_Qh + (size_t)bh * SS * HEADD;
    unsigned qa[2][4];
#pragma unroll
    for (int mt = 0; mt < 2; mt++) {
        const __half* r0 = Qbh + (size_t)(qrow0 + mt * 16 + gr) * HEADD;
        qa[mt][0] = *(const unsigned*)(r0 + 2 * gc);
        qa[mt][1] = *(const unsigned*)(r0 + 8 * HEADD + 2 * gc);
        qa[mt][2] = *(const unsigned*)(r0 + 2 * gc + 8);
        qa[mt][3] = *(const unsigned*)(r0 + 8 * HEADD + 2 * gc + 8);
    }

    const __half* Kbh = g_Kh + (size_t)bh * SS * HEADD;
    const __half* Vbh = g_Vt + (size_t)bh * HEADD * SS;

    // loader roles: threads 0-127 load K (128 uint4), 128-255 load V (128 uint4)
    const int role = tid >> 7;
    const int kr = (tid & 127) >> 1, ko = (tid & 1) * 8;
    const int vt = tid & 127;
    const int vd = vt >> 3, vo = (vt & 7) * 8;

    float4 nx;
    if (role == 0) nx = *(const float4*)(Kbh + (size_t)kr * HEADD + ko);
    else           nx = *(const float4*)(Vbh + (size_t)vd * SS + vo);
    if (role == 0) *(float4*)&Ksh[0][kr][ko] = nx;
    else           *(float4*)&Vts[0][vd][vo] = nx;
    __syncthreads();

    float O[2][3][4] = {};    // [mt][nv-tile][frag]; nv=2 column 16 carries l
    unsigned P[2][8][2];

    for (int c = 0; c < NCH; c++) {
        const int buf = c & 1;
        if (c + 1 < NCH) {
            if (role == 0)
                nx = *(const float4*)(Kbh + (size_t)((c + 1) * BK + kr) * HEADD + ko);
            else
                nx = *(const float4*)(Vbh + (size_t)vd * SS + (c + 1) * BK + vo);
        }

        // ---- S = Q @ K^T, then P = exp2(S) packed fp16 ----
#pragma unroll
        for (int nt = 0; nt < 8; nt++) {
            unsigned b0 = *(const unsigned*)&Ksh[buf][nt * 8 + gr][2 * gc];
            unsigned b1 = *(const unsigned*)&Ksh[buf][nt * 8 + gr][2 * gc + 8];
            float s[4] = {0.f, 0.f, 0.f, 0.f};
            float t[4] = {0.f, 0.f, 0.f, 0.f};
            mma_16816(s, qa[0], b0, b1);
            mma_16816(t, qa[1], b0, b1);
            P[0][nt][0] = h2exp2_fast(packh2(s[0], s[1]));
            P[0][nt][1] = h2exp2_fast(packh2(s[2], s[3]));
            P[1][nt][0] = h2exp2_fast(packh2(t[0], t[1]));
            P[1][nt][1] = h2exp2_fast(packh2(t[2], t[3]));
        }

        // ---- O += P @ Vt (nv=2 tile accumulates l via ones column) ----
#pragma unroll
        for (int kt = 0; kt < 4; kt++) {
            unsigned a0[4] = { P[0][2*kt][0], P[0][2*kt][1],
                               P[0][2*kt+1][0], P[0][2*kt+1][1] };
            unsigned a1[4] = { P[1][2*kt][0], P[1][2*kt][1],
                               P[1][2*kt+1][0], P[1][2*kt+1][1] };
#pragma unroll
            for (int nvt = 0; nvt < 3; nvt++) {
                unsigned b0 = *(const unsigned*)&Vts[buf][nvt * 8 + gr][kt * 16 + 2 * gc];
                unsigned b1 = *(const unsigned*)&Vts[buf][nvt * 8 + gr][kt * 16 + 2 * gc + 8];
                mma_16816(O[0][nvt], a0, b0, b1);
                mma_16816(O[1][nvt], a1, b0, b1);
            }
        }

        __syncthreads();
        if (c + 1 < NCH) {
            if (role == 0) *(float4*)&Ksh[buf ^ 1][kr][ko] = nx;
            else           *(float4*)&Vts[buf ^ 1][vd][vo] = nx;
        }
        __syncthreads();
    }

    // ---- epilogue: normalize by l (column 16) and store ----
    const int b = bh >> 2, h = bh & 3;
#pragma unroll
    for (int mt = 0; mt < 2; mt++) {
        const int srclane = lane & ~3;   // gc==0 lane of this quad holds col 16
        float l_lo = __shfl_sync(0xffffffffu, O[mt][2][0], srclane);
        float l_hi = __shfl_sync(0xffffffffu, O[mt][2][2], srclane);
        const float inv_lo = 1.f / l_lo;
        const float inv_hi = 1.f / l_hi;
        const int r_lo = qrow0 + mt * 16 + gr;
        const int r_hi = r_lo + 8;
#pragma unroll
        for (int nvt = 0; nvt < 2; nvt++) {
            float2 vlo = make_float2(O[mt][nvt][0] * inv_lo, O[mt][nvt][1] * inv_lo);
            float2 vhi = make_float2(O[mt][nvt][2] * inv_hi, O[mt][nvt][3] * inv_hi);
            *(float2*)&g_heads[((size_t)(b * SS) + r_lo) * EMB + h * HEADD + nvt * 8 + 2 * gc] = vlo;
            *(float2*)&g_heads[((size_t)(b * SS) + r_hi) * EMB + h * HEADD + nvt * 8 + 2 * gc] = vhi;
        }
    }
}

// =====================================================================
// Kernel 3: post block on tensor cores. B-frags direct from L1/L2.
// =====================================================================
__global__ void __launch_bounds__(128) post_kernel(
    const float* __restrict__ data,
    const float* __restrict__ bo,
    const float* __restrict__ g1,  const float* __restrict__ bl1,
    const float* __restrict__ b1,  const float* __restrict__ b2,
    const float* __restrict__ g2,  const float* __restrict__ bl2,
    float* __restrict__ out)
{
    const int tid  = threadIdx.x;
    const int warp = tid >> 5;
    const int lane = tid & 31;
    const int gr   = lane >> 2;
    const int gc   = lane & 3;

    const int tile = blockIdx.x * 4 + warp;
    const int tok0 = tile * 16;
    const float* rowL = data + (size_t)(tok0 + gr) * 64;
    const float* rowH = rowL + 8 * 64;

    unsigned a[4][4];
#pragma unroll
    for (int kt = 0; kt < 4; kt++) {
        const float* r0 = g_heads + (size_t)(tok0 + gr) * 64 + kt * 16 + 2 * gc;
        const float* r8 = r0 + 8 * 64;
        float2 x0 = *(const float2*)r0;
        float2 x8 = *(const float2*)r8;
        float2 y0 = *(const float2*)(r0 + 8);
        float2 y8 = *(const float2*)(r8 + 8);
        a[kt][0] = packh2(x0.x, x0.y); a[kt][1] = packh2(x8.x, x8.y);
        a[kt][2] = packh2(y0.x, y0.y); a[kt][3] = packh2(y8.x, y8.y);
    }

    float acc[8][4] = {};
#pragma unroll
    for (int nt = 0; nt < 8; nt++)
#pragma unroll
        for (int kt = 0; kt < 4; kt++) {
            const __half* base = &g_Wpost[(nt * 8 + gr) * 72 + kt * 16 + 2 * gc];
            mma_16816(acc[nt], a[kt], *(const unsigned*)base, *(const unsigned*)(base + 8));
        }

    float x1[8][4];
    float sl = 0.f, sh = 0.f;
#pragma unroll
    for (int nt = 0; nt < 8; nt++) {
        const int col = nt * 8 + 2 * gc;
        float2 dl = *(const float2*)(rowL + col);
        float2 dh = *(const float2*)(rowH + col);
        float2 bb = *(const float2*)(bo + col);
        x1[nt][0] = acc[nt][0] + dl.x + bb.x;
        x1[nt][1] = acc[nt][1] + dl.y + bb.y;
        x1[nt][2] = acc[nt][2] + dh.x + bb.x;
        x1[nt][3] = acc[nt][3] + dh.y + bb.y;
        sl += x1[nt][0] + x1[nt][1];
        sh += x1[nt][2] + x1[nt][3];
    }
    sl += __shfl_xor_sync(0xffffffffu, sl, 1); sl += __shfl_xor_sync(0xffffffffu, sl, 2);
    sh += __shfl_xor_sync(0xffffffffu, sh, 1); sh += __shfl_xor_sync(0xffffffffu, sh, 2);
    float ml = sl * (1.f / 64.f), mh = sh * (1.f / 64.f);
    float vl = 0.f, vh = 0.f;
#pragma unroll
    for (int nt = 0; nt < 8; nt++) {
        x1[nt][0] -= ml; x1[nt][1] -= ml; x1[nt][2] -= mh; x1[nt][3] -= mh;
        vl += x1[nt][0]*x1[nt][0] + x1[nt][1]*x1[nt][1];
        vh += x1[nt][2]*x1[nt][2] + x1[nt][3]*x1[nt][3];
    }
    vl += __shfl_xor_sync(0xffffffffu, vl, 1); vl += __shfl_xor_sync(0xffffffffu, vl, 2);
    vh += __shfl_xor_sync(0xffffffffu, vh, 1); vh += __shfl_xor_sync(0xffffffffu, vh, 2);
    float il = rsqrtf(vl * (1.f / 64.f) + EPS);
    float ih = rsqrtf(vh * (1.f / 64.f) + EPS);
#pragma unroll
    for (int nt = 0; nt < 8; nt++) {
        const int col = nt * 8 + 2 * gc;
        float2 gg = *(const float2*)(g1 + col);
        float2 ee = *(const float2*)(bl1 + col);
        x1[nt][0] = x1[nt][0] * il * gg.x + ee.x;
        x1[nt][1] = x1[nt][1] * il * gg.y + ee.y;
        x1[nt][2] = x1[nt][2] * ih * gg.x + ee.x;
        x1[nt][3] = x1[nt][3] * ih * gg.y + ee.y;
    }

#pragma unroll
    for (int kt = 0; kt < 4; kt++) {
        a[kt][0] = packh2(x1[2*kt][0],   x1[2*kt][1]);
        a[kt][1] = packh2(x1[2*kt][2],   x1[2*kt][3]);
        a[kt][2] = packh2(x1[2*kt+1][0], x1[2*kt+1][1]);
        a[kt][3] = packh2(x1[2*kt+1][2], x1[2*kt+1][3]);
    }
    float acc2[8][4] = {};
#pragma unroll
    for (int nt = 0; nt < 8; nt++)
#pragma unroll
        for (int kt = 0; kt < 4; kt++) {
            const __half* base = &g_Wpost[(64 + nt * 8 + gr) * 72 + kt * 16 + 2 * gc];
            mma_16816(acc2[nt], a[kt], *(const unsigned*)base, *(const unsigned*)(base + 8));
        }

#pragma unroll
    for (int nt = 0; nt < 8; nt++) {
        const int col = nt * 8 + 2 * gc;
        float2 bb = *(const float2*)(b1 + col);
        acc2[nt][0] = fmaxf(acc2[nt][0] + bb.x, 0.f);
        acc2[nt][1] = fmaxf(acc2[nt][1] + bb.y, 0.f);
        acc2[nt][2] = fmaxf(acc2[nt][2] + bb.x, 0.f);
        acc2[nt][3] = fmaxf(acc2[nt][3] + bb.y, 0.f);
    }
#pragma unroll
    for (int kt = 0; kt < 4; kt++) {
        a[kt][0] = packh2(acc2[2*kt][0],   acc2[2*kt][1]);
        a[kt][1] = packh2(acc2[2*kt][2],   acc2[2*kt][3]);
        a[kt][2] = packh2(acc2[2*kt+1][0], acc2[2*kt+1][1]);
        a[kt][3] = packh2(acc2[2*kt+1][2], acc2[2*kt+1][3]);
    }

    float acc3[8][4] = {};
#pragma unroll
    for (int nt = 0; nt < 8; nt++)
#pragma unroll
        for (int kt = 0; kt < 4; kt++) {
            const __half* base = &g_Wpost[(128 + nt * 8 + gr) * 72 + kt * 16 + 2 * gc];
            mma_16816(acc3[nt], a[kt], *(const unsigned*)base, *(const unsigned*)(base + 8));
        }

    sl = 0.f; sh = 0.f;
#pragma unroll
    for (int nt = 0; nt < 8; nt++) {
        const int col = nt * 8 + 2 * gc;
        float2 bb = *(const float2*)(b2 + col);
        acc3[nt][0] += bb.x + x1[nt][0];
        acc3[nt][1] += bb.y + x1[nt][1];
        acc3[nt][2] += bb.x + x1[nt][2];
        acc3[nt][3] += bb.y + x1[nt][3];
        sl += acc3[nt][0] + acc3[nt][1];
        sh += acc3[nt][2] + acc3[nt][3];
    }
    sl += __shfl_xor_sync(0xffffffffu, sl, 1); sl += __shfl_xor_sync(0xffffffffu, sl, 2);
    sh += __shfl_xor_sync(0xffffffffu, sh, 1); sh += __shfl_xor_sync(0xffffffffu, sh, 2);
    ml = sl * (1.f / 64.f); mh = sh * (1.f / 64.f);
    vl = 0.f; vh = 0.f;
#pragma unroll
    for (int nt = 0; nt < 8; nt++) {
        acc3[nt][0] -= ml; acc3[nt][1] -= ml; acc3[nt][2] -= mh; acc3[nt][3] -= mh;
        vl += acc3[nt][0]*acc3[nt][0] + acc3[nt][1]*acc3[nt][1];
        vh += acc3[nt][2]*acc3[nt][2] + acc3[nt][3]*acc3[nt][3];
    }
    vl += __shfl_xor_sync(0xffffffffu, vl, 1); vl += __shfl_xor_sync(0xffffffffu, vl, 2);
    vh += __shfl_xor_sync(0xffffffffu, vh, 1); vh += __shfl_xor_sync(0xffffffffu, vh, 2);
    il = rsqrtf(vl * (1.f / 64.f) + EPS);
    ih = rsqrtf(vh * (1.f / 64.f) + EPS);

    float* outL = out + (size_t)(tok0 + gr) * 64;
    float* outH = outL + 8 * 64;
#pragma unroll
    for (int nt = 0; nt < 8; nt++) {
        const int col = nt * 8 + 2 * gc;
        float2 gg = *(const float2*)(g2 + col);
        float2 ee = *(const float2*)(bl2 + col);
        *(float2*)(outL + col) = make_float2(acc3[nt][0] * il * gg.x + ee.x,
                                             acc3[nt][1] * il * gg.y + ee.y);
        *(float2*)(outH + col) = make_float2(acc3[nt][2] * ih * gg.x + ee.x,
                                             acc3[nt][3] * ih * gg.y + ee.y);
    }
}

// =====================================================================
extern "C" void kernel_launch(void* const* d_in, const int* in_sizes, int n_in,
                              void* d_out, int out_size)
{
    const float* data  = (const float*)d_in[0];
    const float* Wq    = (const float*)d_in[1];
    const float* Wk    = (const float*)d_in[2];
    const float* Wv    = (const float*)d_in[3];
    const float* Wo    = (const float*)d_in[4];
    const float* bo    = (const float*)d_in[5];
    const float* ln1_g = (const float*)d_in[6];
    const float* ln1_b = (const float*)d_in[7];
    const float* W1    = (const float*)d_in[8];
    const float* b1    = (const float*)d_in[9];
    const float* W2    = (const float*)d_in[10];
    const float* b2    = (const float*)d_in[11];
    const float* ln2_g = (const float*)d_in[12];
    const float* ln2_b = (const float*)d_in[13];
    float* out = (float*)d_out;

    prep_kernel<<<96, 256>>>(Wq, Wk, Wv, Wo, W1, W2);
    qkv_kernel<<<256, 128>>>(data);
    attn_kernel<<<dim3(NHEAD * BB, SS / 256), 256>>>();
    post_kernel<<<256, 128>>>(data, bo, ln1_g, ln1_b, b1, b2, ln2_g, ln2_b, out);
}

// round 14
// speedup vs baseline: 1.1470x; 1.1470x over previous
#include <cuda_runtime.h>
#include <cuda_fp16.h>
#include <math.h>

#define EMB    64
#define NHEAD  4
#define HEADD  16
#define BB     8
#define SS     2048
#define NTOK   (BB*SS)            // 16384
#define NROW   (NTOK*NHEAD/... )
#define EPS    1e-5f
// exp2-domain scale: 1/sqrt(16) * log2(e)
#define QSCALE (0.25f * 1.44269504088896f)

#define BK     64                 // keys per chunk
#define NCH    (SS/BK)            // 32
#define NSPLIT 4
#define CPS    (NCH/NSPLIT)       // 8 chunks per split
#define NROWS  (32*SS)            // 65536 (bh x s)

// ---------------- device scratch (no allocations allowed) ----------------
__device__ __align__(16) __half g_Qh[NTOK*EMB];   // [bh][s][16], QSCALE folded in
__device__ __align__(16) __half g_Kh[NTOK*EMB];   // [bh][s][16]
__device__ __align__(16) __half g_Vt[NTOK*EMB];   // [bh][16][s]  (transposed!)
__device__ __align__(16) float  g_heads[NTOK*EMB];  // concat layout [b][s][h*16+k]
__device__ __align__(16) __half g_Wth[192*72];    // QKV weights [n][k]
__device__ __align__(16) __half g_Wpost[3*64*72]; // Wo|W1|W2 [n][k]
__device__ __align__(16) float  g_Opart[NSPLIT*NROWS*HEADD]; // 16 MB partials
__device__ __align__(16) float  g_lpart[NSPLIT*NROWS];       // 1 MB

__device__ __forceinline__ void mma_16816(float* d, const unsigned* a,
                                          unsigned b0, unsigned b1) {
    asm volatile(
        "mma.sync.aligned.m16n8k16.row.col.f32.f16.f16.f32 "
        "{%0,%1,%2,%3}, {%4,%5,%6,%7}, {%8,%9}, {%0,%1,%2,%3};\n"
        : "+f"(d[0]), "+f"(d[1]), "+f"(d[2]), "+f"(d[3])
        : "r"(a[0]), "r"(a[1]), "r"(a[2]), "r"(a[3]), "r"(b0), "r"(b1));
}

__device__ __forceinline__ unsigned packh2(float x, float y) {
    __half2 h = __floats2half2_rn(x, y);
    return *(unsigned*)&h;
}

__device__ __forceinline__ unsigned h2exp2_fast(unsigned x) {
    unsigned r;
    asm("ex2.approx.f16x2 %0, %1;" : "=r"(r) : "r"(x));
    return r;
}

// =====================================================================
// Kernel 0: one-time weight conversion to fp16 B-fragment layouts.
// =====================================================================
__global__ void prep_kernel(const float* __restrict__ Wq,
                            const float* __restrict__ Wk,
                            const float* __restrict__ Wv,
                            const float* __restrict__ Wo,
                            const float* __restrict__ W1,
                            const float* __restrict__ W2)
{
    const int i = blockIdx.x * 256 + threadIdx.x;
    if (i < 192 * 64) {
        const int n = i % 192, k = i / 192;
        float w;
        if (n < 64)        w = Wq[(n >> 4) * 1024 + k * 16 + (n & 15)] * QSCALE;
        else if (n < 128)  w = Wk[((n - 64) >> 4) * 1024 + k * 16 + ((n - 64) & 15)];
        else               w = Wv[((n - 128) >> 4) * 1024 + k * 16 + ((n - 128) & 15)];
        g_Wth[n * 72 + k] = __float2half_rn(w);
    } else if (i < 192 * 64 + 3 * 64 * 64) {
        const int j = i - 192 * 64;
        const int m = j >> 12;          // 0 Wo, 1 W1, 2 W2
        const int r = j & 4095;
        const int n = r & 63, k = r >> 6;
        const float* W = (m == 0) ? Wo : (m == 1) ? W1 : W2;
        g_Wpost[(m * 64 + n) * 72 + k] = __float2half_rn(W[k * 64 + n]);
    }
}

// =====================================================================
// Kernel 1: QKV projection on tensor cores. B-frags direct from L1/L2.
// =====================================================================
__global__ void __launch_bounds__(128) qkv_kernel(const float* __restrict__ data)
{
    __shared__ __align__(16) __half stage_v[64 * 66]; // 8448 B

    const int tid  = threadIdx.x;
    const int warp = tid >> 5;
    const int lane = tid & 31;
    const int gr   = lane >> 2;
    const int gc   = lane & 3;

    const int tile = blockIdx.x * 4 + warp;
    const int tok0 = tile * 16;

    unsigned a[4][4];
#pragma unroll
    for (int kt = 0; kt < 4; kt++) {
        const float* r0 = data + (size_t)(tok0 + gr) * 64 + kt * 16 + 2 * gc;
        const float* r8 = r0 + 8 * 64;
        float2 x0 = *(const float2*)r0;
        float2 x8 = *(const float2*)r8;
        float2 y0 = *(const float2*)(r0 + 8);
        float2 y8 = *(const float2*)(r8 + 8);
        a[kt][0] = packh2(x0.x, x0.y); a[kt][1] = packh2(x8.x, x8.y);
        a[kt][2] = packh2(y0.x, y0.y); a[kt][3] = packh2(y8.x, y8.y);
    }

    float acc[24][4] = {};
#pragma unroll
    for (int nt = 0; nt < 24; nt++) {
#pragma unroll
        for (int kt = 0; kt < 4; kt++) {
            const __half* base = &g_Wth[(nt * 8 + gr) * 72 + kt * 16 + 2 * gc];
            unsigned b0 = *(const unsigned*)base;
            unsigned b1 = *(const unsigned*)(base + 8);
            mma_16816(acc[nt], a[kt], b0, b1);
        }
    }

#pragma unroll
    for (int nt = 0; nt < 8; nt++) {
        const int vcol = nt * 8 + 2 * gc;
        *(__half2*)&stage_v[(warp * 16 + gr)     * 66 + vcol] =
            __floats2half2_rn(acc[16 + nt][0], acc[16 + nt][1]);
        *(__half2*)&stage_v[(warp * 16 + gr + 8) * 66 + vcol] =
            __floats2half2_rn(acc[16 + nt][2], acc[16 + nt][3]);
    }
    __syncthreads();

    const int b  = tok0 >> 11;
    const int sb = tok0 & 2047;
#pragma unroll
    for (int nt = 0; nt < 8; nt++) {           // Q
        const int head = nt >> 1;
        const int kk0  = (nt & 1) * 8 + 2 * gc;
        const size_t base = (size_t)(b * 4 + head) * 2048;
        *(__half2*)&g_Qh[(base + sb + gr)     * 16 + kk0] = __floats2half2_rn(acc[nt][0], acc[nt][1]);
        *(__half2*)&g_Qh[(base + sb + gr + 8) * 16 + kk0] = __floats2half2_rn(acc[nt][2], acc[nt][3]);
    }
#pragma unroll
    for (int nt = 0; nt < 8; nt++) {           // K
        const int head = nt >> 1;
        const int kk0  = (nt & 1) * 8 + 2 * gc;
        const size_t base = (size_t)(b * 4 + head) * 2048;
        *(__half2*)&g_Kh[(base + sb + gr)     * 16 + kk0] = __floats2half2_rn(acc[8 + nt][0], acc[8 + nt][1]);
        *(__half2*)&g_Kh[(base + sb + gr + 8) * 16 + kk0] = __floats2half2_rn(acc[8 + nt][2], acc[8 + nt][3]);
    }

    const int s0 = (blockIdx.x * 64) & 2047;
    const int bb = (blockIdx.x * 64) >> 11;
#pragma unroll
    for (int q = 0; q < 4; q++) {
        const int idx = q * 128 + tid;
        const int c   = idx >> 3;
        const int j   = idx & 7;
        const int h   = c >> 4;
        const int kk  = c & 15;
        __half2 p0 = __halves2half2(stage_v[(8*j+0)*66+c], stage_v[(8*j+1)*66+c]);
        __half2 p1 = __halves2half2(stage_v[(8*j+2)*66+c], stage_v[(8*j+3)*66+c]);
        __half2 p2 = __halves2half2(stage_v[(8*j+4)*66+c], stage_v[(8*j+5)*66+c]);
        __half2 p3 = __halves2half2(stage_v[(8*j+6)*66+c], stage_v[(8*j+7)*66+c]);
        uint4 u;
        u.x = *(unsigned*)&p0; u.y = *(unsigned*)&p1;
        u.z = *(unsigned*)&p2; u.w = *(unsigned*)&p3;
        *(uint4*)&g_Vt[((size_t)(bb * 4 + h) * 16 + kk) * 2048 + s0 + 8 * j] = u;
    }
}

// =====================================================================
// Kernel 2: split-K flash attention. Block = (bh, q-slab 128, kv-split).
// Each block handles 8 chunks (512 keys) and writes UNNORMALIZED partial
// O and l. No-max softmax => partials are plain sums (associative).
// =====================================================================
__global__ void __launch_bounds__(128) attn_kernel()
{
    __shared__ __align__(16) __half Ksh[2][BK][24];   // stride 24 halves
    __shared__ __align__(16) __half Vts[2][24][72];   // [dim(+l cols)][key]

    const int bh    = blockIdx.x;
    const int split = blockIdx.z;
    const int tid   = threadIdx.x;
    const int warp  = tid >> 5;
    const int lane  = tid & 31;
    const int gr    = lane >> 2;
    const int gc    = lane & 3;
    const int qrow0 = blockIdx.y * 128 + warp * 32;
    const int c0    = split * CPS;

    // constant rows 16..23 of Vt tiles: dim16 = ones (row-sum column), rest 0
    for (int i = tid; i < 2 * 8 * 72; i += 128) {
        int bufi = i / (8 * 72);
        int rem  = i % (8 * 72);
        int r = rem / 72, cc = rem % 72;
        Vts[bufi][16 + r][cc] = __float2half(r == 0 ? 1.0f : 0.0f);
    }

    // Q fragments (held for whole kernel)
    const __half* Qbh = g_Qh + (size_t)bh * SS * HEADD;
    unsigned qa[2][4];
#pragma unroll
    for (int mt = 0; mt < 2; mt++) {
        const __half* r0 = Qbh + (size_t)(qrow0 + mt * 16 + gr) * HEADD;
        qa[mt][0] = *(const unsigned*)(r0 + 2 * gc);
        qa[mt][1] = *(const unsigned*)(r0 + 8 * HEADD + 2 * gc);
        qa[mt][2] = *(const unsigned*)(r0 + 2 * gc + 8);
        qa[mt][3] = *(const unsigned*)(r0 + 8 * HEADD + 2 * gc + 8);
    }

    const __half* Kbh = g_Kh + (size_t)bh * SS * HEADD;
    const __half* Vbh = g_Vt + (size_t)bh * HEADD * SS;

    const int kr = tid >> 1, ko = (tid & 1) * 8;   // K: row, half-offset
    const int vd = tid >> 3, vo = (tid & 7) * 8;   // V: dim, key-offset

    float4 nk = *(const float4*)(Kbh + (size_t)(c0 * BK + kr) * HEADD + ko);
    float4 nv = *(const float4*)(Vbh + (size_t)vd * SS + c0 * BK + vo);
    *(float4*)&Ksh[0][kr][ko] = nk;
    *(float4*)&Vts[0][vd][vo] = nv;
    __syncthreads();

    float O[2][3][4] = {};    // [mt][nv-tile][frag]; nv=2 column 16 carries l
    unsigned P[2][8][2];

    for (int cc = 0; cc < CPS; cc++) {
        const int c   = c0 + cc;
        const int buf = cc & 1;
        if (cc + 1 < CPS) {
            nk = *(const float4*)(Kbh + (size_t)((c + 1) * BK + kr) * HEADD + ko);
            nv = *(const float4*)(Vbh + (size_t)vd * SS + (c + 1) * BK + vo);
        }

        // ---- S = Q @ K^T, then P = exp2(S) packed fp16 ----
#pragma unroll
        for (int nt = 0; nt < 8; nt++) {
            unsigned b0 = *(const unsigned*)&Ksh[buf][nt * 8 + gr][2 * gc];
            unsigned b1 = *(const unsigned*)&Ksh[buf][nt * 8 + gr][2 * gc + 8];
            float s[4] = {0.f, 0.f, 0.f, 0.f};
            float t[4] = {0.f, 0.f, 0.f, 0.f};
            mma_16816(s, qa[0], b0, b1);
            mma_16816(t, qa[1], b0, b1);
            P[0][nt][0] = h2exp2_fast(packh2(s[0], s[1]));
            P[0][nt][1] = h2exp2_fast(packh2(s[2], s[3]));
            P[1][nt][0] = h2exp2_fast(packh2(t[0], t[1]));
            P[1][nt][1] = h2exp2_fast(packh2(t[2], t[3]));
        }

        // ---- O += P @ Vt (nv=2 tile accumulates l via ones column) ----
#pragma unroll
        for (int kt = 0; kt < 4; kt++) {
            unsigned a0[4] = { P[0][2*kt][0], P[0][2*kt][1],
                               P[0][2*kt+1][0], P[0][2*kt+1][1] };
            unsigned a1[4] = { P[1][2*kt][0], P[1][2*kt][1],
                               P[1][2*kt+1][0], P[1][2*kt+1][1] };
#pragma unroll
            for (int nvt = 0; nvt < 3; nvt++) {
                unsigned b0 = *(const unsigned*)&Vts[buf][nvt * 8 + gr][kt * 16 + 2 * gc];
                unsigned b1 = *(const unsigned*)&Vts[buf][nvt * 8 + gr][kt * 16 + 2 * gc + 8];
                mma_16816(O[0][nvt], a0, b0, b1);
                mma_16816(O[1][nvt], a1, b0, b1);
            }
        }

        __syncthreads();
        if (cc + 1 < CPS) {
            *(float4*)&Ksh[buf ^ 1][kr][ko] = nk;
            *(float4*)&Vts[buf ^ 1][vd][vo] = nv;
        }
        __syncthreads();
    }

    // ---- epilogue: store UNNORMALIZED partial O and l ----
    const size_t rowbase = (size_t)split * NROWS + (size_t)bh * SS;
#pragma unroll
    for (int mt = 0; mt < 2; mt++) {
        const int r_lo = qrow0 + mt * 16 + gr;
        const int r_hi = r_lo + 8;
#pragma unroll
        for (int nvt = 0; nvt < 2; nvt++) {
            *(float2*)&g_Opart[(rowbase + r_lo) * HEADD + nvt * 8 + 2 * gc] =
                make_float2(O[mt][nvt][0], O[mt][nvt][1]);
            *(float2*)&g_Opart[(rowbase + r_hi) * HEADD + nvt * 8 + 2 * gc] =
                make_float2(O[mt][nvt][2], O[mt][nvt][3]);
        }
        if (gc == 0) {
            g_lpart[rowbase + r_lo] = O[mt][2][0];
            g_lpart[rowbase + r_hi] = O[mt][2][2];
        }
    }
}

// =====================================================================
// Kernel 2b: reduce splits -> g_heads.  thread = (row, 4-dim group).
// =====================================================================
__global__ void __launch_bounds__(256) reduce_kernel()
{
    const int idx = blockIdx.x * 256 + threadIdx.x;   // 0..262143
    const int row = idx >> 2;
    const int d4  = idx & 3;

    float4 acc = make_float4(0.f, 0.f, 0.f, 0.f);
    float l = 0.f;
#pragma unroll
    for (int sp = 0; sp < NSPLIT; sp++) {
        float4 v = *(const float4*)&g_Opart[((size_t)sp * NROWS + row) * HEADD + d4 * 4];
        acc.x += v.x; acc.y += v.y; acc.z += v.z; acc.w += v.w;
        l += g_lpart[(size_t)sp * NROWS + row];
    }
    const float inv = 1.f / l;
    const int bh = row >> 11, s = row & 2047;
    const int b = bh >> 2, h = bh & 3;
    *(float4*)&g_heads[((size_t)(b * SS + s)) * EMB + h * HEADD + d4 * 4] =
        make_float4(acc.x * inv, acc.y * inv, acc.z * inv, acc.w * inv);
}

// =====================================================================
// Kernel 3: post block on tensor cores. B-frags direct from L1/L2.
// =====================================================================
__global__ void __launch_bounds__(128) post_kernel(
    const float* __restrict__ data,
    const float* __restrict__ bo,
    const float* __restrict__ g1,  const float* __restrict__ bl1,
    const float* __restrict__ b1,  const float* __restrict__ b2,
    const float* __restrict__ g2,  const float* __restrict__ bl2,
    float* __restrict__ out)
{
    const int tid  = threadIdx.x;
    const int warp = tid >> 5;
    const int lane = tid & 31;
    const int gr   = lane >> 2;
    const int gc   = lane & 3;

    const int tile = blockIdx.x * 4 + warp;
    const int tok0 = tile * 16;
    const float* rowL = data + (size_t)(tok0 + gr) * 64;
    const float* rowH = rowL + 8 * 64;

    unsigned a[4][4];
#pragma unroll
    for (int kt = 0; kt < 4; kt++) {
        const float* r0 = g_heads + (size_t)(tok0 + gr) * 64 + kt * 16 + 2 * gc;
        const float* r8 = r0 + 8 * 64;
        float2 x0 = *(const float2*)r0;
        float2 x8 = *(const float2*)r8;
        float2 y0 = *(const float2*)(r0 + 8);
        float2 y8 = *(const float2*)(r8 + 8);
        a[kt][0] = packh2(x0.x, x0.y); a[kt][1] = packh2(x8.x, x8.y);
        a[kt][2] = packh2(y0.x, y0.y); a[kt][3] = packh2(y8.x, y8.y);
    }

    float acc[8][4] = {};
#pragma unroll
    for (int nt = 0; nt < 8; nt++)
#pragma unroll
        for (int kt = 0; kt < 4; kt++) {
            const __half* base = &g_Wpost[(nt * 8 + gr) * 72 + kt * 16 + 2 * gc];
            mma_16816(acc[nt], a[kt], *(const unsigned*)base, *(const unsigned*)(base + 8));
        }

    float x1[8][4];
    float sl = 0.f, sh = 0.f;
#pragma unroll
    for (int nt = 0; nt < 8; nt++) {
        const int col = nt * 8 + 2 * gc;
        float2 dl = *(const float2*)(rowL + col);
        float2 dh = *(const float2*)(rowH + col);
        float2 bb = *(const float2*)(bo + col);
        x1[nt][0] = acc[nt][0] + dl.x + bb.x;
        x1[nt][1] = acc[nt][1] + dl.y + bb.y;
        x1[nt][2] = acc[nt][2] + dh.x + bb.x;
        x1[nt][3] = acc[nt][3] + dh.y + bb.y;
        sl += x1[nt][0] + x1[nt][1];
        sh += x1[nt][2] + x1[nt][3];
    }
    sl += __shfl_xor_sync(0xffffffffu, sl, 1); sl += __shfl_xor_sync(0xffffffffu, sl, 2);
    sh += __shfl_xor_sync(0xffffffffu, sh, 1); sh += __shfl_xor_sync(0xffffffffu, sh, 2);
    float ml = sl * (1.f / 64.f), mh = sh * (1.f / 64.f);
    float vl = 0.f, vh = 0.f;
#pragma unroll
    for (int nt = 0; nt < 8; nt++) {
        x1[nt][0] -= ml; x1[nt][1] -= ml; x1[nt][2] -= mh; x1[nt][3] -= mh;
        vl += x1[nt][0]*x1[nt][0] + x1[nt][1]*x1[nt][1];
        vh += x1[nt][2]*x1[nt][2] + x1[nt][3]*x1[nt][3];
    }
    vl += __shfl_xor_sync(0xffffffffu, vl, 1); vl += __shfl_xor_sync(0xffffffffu, vl, 2);
    vh += __shfl_xor_sync(0xffffffffu, vh, 1); vh += __shfl_xor_sync(0xffffffffu, vh, 2);
    float il = rsqrtf(vl * (1.f / 64.f) + EPS);
    float ih = rsqrtf(vh * (1.f / 64.f) + EPS);
#pragma unroll
    for (int nt = 0; nt < 8; nt++) {
        const int col = nt * 8 + 2 * gc;
        float2 gg = *(const float2*)(g1 + col);
        float2 ee = *(const float2*)(bl1 + col);
        x1[nt][0] = x1[nt][0] * il * gg.x + ee.x;
        x1[nt][1] = x1[nt][1] * il * gg.y + ee.y;
        x1[nt][2] = x1[nt][2] * ih * gg.x + ee.x;
        x1[nt][3] = x1[nt][3] * ih * gg.y + ee.y;
    }

#pragma unroll
    for (int kt = 0; kt < 4; kt++) {
        a[kt][0] = packh2(x1[2*kt][0],   x1[2*kt][1]);
        a[kt][1] = packh2(x1[2*kt][2],   x1[2*kt][3]);
        a[kt][2] = packh2(x1[2*kt+1][0], x1[2*kt+1][1]);
        a[kt][3] = packh2(x1[2*kt+1][2], x1[2*kt+1][3]);
    }
    float acc2[8][4] = {};
#pragma unroll
    for (int nt = 0; nt < 8; nt++)
#pragma unroll
        for (int kt = 0; kt < 4; kt++) {
            const __half* base = &g_Wpost[(64 + nt * 8 + gr) * 72 + kt * 16 + 2 * gc];
            mma_16816(acc2[nt], a[kt], *(const unsigned*)base, *(const unsigned*)(base + 8));
        }

#pragma unroll
    for (int nt = 0; nt < 8; nt++) {
        const int col = nt * 8 + 2 * gc;
        float2 bb = *(const float2*)(b1 + col);
        acc2[nt][0] = fmaxf(acc2[nt][0] + bb.x, 0.f);
        acc2[nt][1] = fmaxf(acc2[nt][1] + bb.y, 0.f);
        acc2[nt][2] = fmaxf(acc2[nt][2] + bb.x, 0.f);
        acc2[nt][3] = fmaxf(acc2[nt][3] + bb.y, 0.f);
    }
#pragma unroll
    for (int kt = 0; kt < 4; kt++) {
        a[kt][0] = packh2(acc2[2*kt][0],   acc2[2*kt][1]);
        a[kt][1] = packh2(acc2[2*kt][2],   acc2[2*kt][3]);
        a[kt][2] = packh2(acc2[2*kt+1][0], acc2[2*kt+1][1]);
        a[kt][3] = packh2(acc2[2*kt+1][2], acc2[2*kt+1][3]);
    }

    float acc3[8][4] = {};
#pragma unroll
    for (int nt = 0; nt < 8; nt++)
#pragma unroll
        for (int kt = 0; kt < 4; kt++) {
            const __half* base = &g_Wpost[(128 + nt * 8 + gr) * 72 + kt * 16 + 2 * gc];
            mma_16816(acc3[nt], a[kt], *(const unsigned*)base, *(const unsigned*)(base + 8));
        }

    sl = 0.f; sh = 0.f;
#pragma unroll
    for (int nt = 0; nt < 8; nt++) {
        const int col = nt * 8 + 2 * gc;
        float2 bb = *(const float2*)(b2 + col);
        acc3[nt][0] += bb.x + x1[nt][0];
        acc3[nt][1] += bb.y + x1[nt][1];
        acc3[nt][2] += bb.x + x1[nt][2];
        acc3[nt][3] += bb.y + x1[nt][3];
        sl += acc3[nt][0] + acc3[nt][1];
        sh += acc3[nt][2] + acc3[nt][3];
    }
    sl += __shfl_xor_sync(0xffffffffu, sl, 1); sl += __shfl_xor_sync(0xffffffffu, sl, 2);
    sh += __shfl_xor_sync(0xffffffffu, sh, 1); sh += __shfl_xor_sync(0xffffffffu, sh, 2);
    ml = sl * (1.f / 64.f); mh = sh * (1.f / 64.f);
    vl = 0.f; vh = 0.f;
#pragma unroll
    for (int nt = 0; nt < 8; nt++) {
        acc3[nt][0] -= ml; acc3[nt][1] -= ml; acc3[nt][2] -= mh; acc3[nt][3] -= mh;
        vl += acc3[nt][0]*acc3[nt][0] + acc3[nt][1]*acc3[nt][1];
        vh += acc3[nt][2]*acc3[nt][2] + acc3[nt][3]*acc3[nt][3];
    }
    vl += __shfl_xor_sync(0xffffffffu, vl, 1); vl += __shfl_xor_sync(0xffffffffu, vl, 2);
    vh += __shfl_xor_sync(0xffffffffu, vh, 1); vh += __shfl_xor_sync(0xffffffffu, vh, 2);
    il = rsqrtf(vl * (1.f / 64.f) + EPS);
    ih = rsqrtf(vh * (1.f / 64.f) + EPS);

    float* outL = out + (size_t)(tok0 + gr) * 64;
    float* outH = outL + 8 * 64;
#pragma unroll
    for (int nt = 0; nt < 8; nt++) {
        const int col = nt * 8 + 2 * gc;
        float2 gg = *(const float2*)(g2 + col);
        float2 ee = *(const float2*)(bl2 + col);
        *(float2*)(outL + col) = make_float2(acc3[nt][0] * il * gg.x + ee.x,
                                             acc3[nt][1] * il * gg.y + ee.y);
        *(float2*)(outH + col) = make_float2(acc3[nt][2] * ih * gg.x + ee.x,
                                             acc3[nt][3] * ih * gg.y + ee.y);
    }
}

// =====================================================================
extern "C" void kernel_launch(void* const* d_in, const int* in_sizes, int n_in,
                              void* d_out, int out_size)
{
    const float* data  = (const float*)d_in[0];
    const float* Wq    = (const float*)d_in[1];
    const float* Wk    = (const float*)d_in[2];
    const float* Wv    = (const float*)d_in[3];
    const float* Wo    = (const float*)d_in[4];
    const float* bo    = (const float*)d_in[5];
    const float* ln1_g = (const float*)d_in[6];
    const float* ln1_b = (const float*)d_in[7];
    const float* W1    = (const float*)d_in[8];
    const float* b1    = (const float*)d_in[9];
    const float* W2    = (const float*)d_in[10];
    const float* b2    = (const float*)d_in[11];
    const float* ln2_g = (const float*)d_in[12];
    const float* ln2_b = (const float*)d_in[13];
    float* out = (float*)d_out;

    prep_kernel<<<96, 256>>>(Wq, Wk, Wv, Wo, W1, W2);
    qkv_kernel<<<256, 128>>>(data);
    attn_kernel<<<dim3(NHEAD * BB, SS / 128, NSPLIT), 128>>>();
    reduce_kernel<<<1024, 256>>>();
    post_kernel<<<256, 128>>>(data, bo, ln1_g, ln1_b, b1, b2, ln2_g, ln2_b, out);
}

// round 15
// speedup vs baseline: 1.1475x; 1.0005x over previous
#include <cuda_runtime.h>
#include <cuda_fp16.h>
#include <math.h>

#define EMB    64
#define NHEAD  4
#define HEADD  16
#define BB     8
#define SS     2048
#define NTOK   (BB*SS)            // 16384
#define EPS    1e-5f
// exp2-domain scale: 1/sqrt(16) * log2(e)
#define QSCALE (0.25f * 1.44269504088896f)

#define BK     64                 // keys per chunk
#define NCH    (SS/BK)            // 32
#define NSPLIT 4
#define CPS    (NCH/NSPLIT)       // 8 chunks per split
#define NROWS  (32*SS)            // 65536 (bh x s)

// ---------------- device scratch (no allocations allowed) ----------------
__device__ __align__(16) __half g_Qh[NTOK*EMB];   // [bh][s][16], QSCALE folded in
__device__ __align__(16) __half g_Kh[NTOK*EMB];   // [bh][s][16]
__device__ __align__(16) __half g_Vt[NTOK*EMB];   // [bh][16][s]  (transposed!)
__device__ __align__(16) __half g_Wth[192*72];    // QKV weights [n][k]
__device__ __align__(16) __half g_Wpost[3*64*72]; // Wo|W1|W2 [n][k]
__device__ __align__(16) float  g_Opart[NSPLIT*NROWS*HEADD]; // 16 MB partials
__device__ __align__(16) float  g_lpart[NSPLIT*NROWS];       // 1 MB

__device__ __forceinline__ void mma_16816(float* d, const unsigned* a,
                                          unsigned b0, unsigned b1) {
    asm volatile(
        "mma.sync.aligned.m16n8k16.row.col.f32.f16.f16.f32 "
        "{%0,%1,%2,%3}, {%4,%5,%6,%7}, {%8,%9}, {%0,%1,%2,%3};\n"
        : "+f"(d[0]), "+f"(d[1]), "+f"(d[2]), "+f"(d[3])
        : "r"(a[0]), "r"(a[1]), "r"(a[2]), "r"(a[3]), "r"(b0), "r"(b1));
}

__device__ __forceinline__ unsigned packh2(float x, float y) {
    __half2 h = __floats2half2_rn(x, y);
    return *(unsigned*)&h;
}

__device__ __forceinline__ unsigned h2exp2_fast(unsigned x) {
    unsigned r;
    asm("ex2.approx.f16x2 %0, %1;" : "=r"(r) : "r"(x));
    return r;
}

// =====================================================================
// Kernel 0: one-time weight conversion to fp16 B-fragment layouts.
// =====================================================================
__global__ void prep_kernel(const float* __restrict__ Wq,
                            const float* __restrict__ Wk,
                            const float* __restrict__ Wv,
                            const float* __restrict__ Wo,
                            const float* __restrict__ W1,
                            const float* __restrict__ W2)
{
    const int i = blockIdx.x * 256 + threadIdx.x;
    if (i < 192 * 64) {
        const int n = i % 192, k = i / 192;
        float w;
        if (n < 64)        w = Wq[(n >> 4) * 1024 + k * 16 + (n & 15)] * QSCALE;
        else if (n < 128)  w = Wk[((n - 64) >> 4) * 1024 + k * 16 + ((n - 64) & 15)];
        else               w = Wv[((n - 128) >> 4) * 1024 + k * 16 + ((n - 128) & 15)];
        g_Wth[n * 72 + k] = __float2half_rn(w);
    } else if (i < 192 * 64 + 3 * 64 * 64) {
        const int j = i - 192 * 64;
        const int m = j >> 12;          // 0 Wo, 1 W1, 2 W2
        const int r = j & 4095;
        const int n = r & 63, k = r >> 6;
        const float* W = (m == 0) ? Wo : (m == 1) ? W1 : W2;
        g_Wpost[(m * 64 + n) * 72 + k] = __float2half_rn(W[k * 64 + n]);
    }
}

// =====================================================================
// Kernel 1: QKV projection on tensor cores. B-frags direct from L1/L2.
// =====================================================================
__global__ void __launch_bounds__(128) qkv_kernel(const float* __restrict__ data)
{
    __shared__ __align__(16) __half stage_v[64 * 66]; // 8448 B

    const int tid  = threadIdx.x;
    const int warp = tid >> 5;
    const int lane = tid & 31;
    const int gr   = lane >> 2;
    const int gc   = lane & 3;

    const int tile = blockIdx.x * 4 + warp;
    const int tok0 = tile * 16;

    unsigned a[4][4];
#pragma unroll
    for (int kt = 0; kt < 4; kt++) {
        const float* r0 = data + (size_t)(tok0 + gr) * 64 + kt * 16 + 2 * gc;
        const float* r8 = r0 + 8 * 64;
        float2 x0 = *(const float2*)r0;
        float2 x8 = *(const float2*)r8;
        float2 y0 = *(const float2*)(r0 + 8);
        float2 y8 = *(const float2*)(r8 + 8);
        a[kt][0] = packh2(x0.x, x0.y); a[kt][1] = packh2(x8.x, x8.y);
        a[kt][2] = packh2(y0.x, y0.y); a[kt][3] = packh2(y8.x, y8.y);
    }

    float acc[24][4] = {};
#pragma unroll
    for (int nt = 0; nt < 24; nt++) {
#pragma unroll
        for (int kt = 0; kt < 4; kt++) {
            const __half* base = &g_Wth[(nt * 8 + gr) * 72 + kt * 16 + 2 * gc];
            unsigned b0 = *(const unsigned*)base;
            unsigned b1 = *(const unsigned*)(base + 8);
            mma_16816(acc[nt], a[kt], b0, b1);
        }
    }

#pragma unroll
    for (int nt = 0; nt < 8; nt++) {
        const int vcol = nt * 8 + 2 * gc;
        *(__half2*)&stage_v[(warp * 16 + gr)     * 66 + vcol] =
            __floats2half2_rn(acc[16 + nt][0], acc[16 + nt][1]);
        *(__half2*)&stage_v[(warp * 16 + gr + 8) * 66 + vcol] =
            __floats2half2_rn(acc[16 + nt][2], acc[16 + nt][3]);
    }
    __syncthreads();

    const int b  = tok0 >> 11;
    const int sb = tok0 & 2047;
#pragma unroll
    for (int nt = 0; nt < 8; nt++) {           // Q
        const int head = nt >> 1;
        const int kk0  = (nt & 1) * 8 + 2 * gc;
        const size_t base = (size_t)(b * 4 + head) * 2048;
        *(__half2*)&g_Qh[(base + sb + gr)     * 16 + kk0] = __floats2half2_rn(acc[nt][0], acc[nt][1]);
        *(__half2*)&g_Qh[(base + sb + gr + 8) * 16 + kk0] = __floats2half2_rn(acc[nt][2], acc[nt][3]);
    }
#pragma unroll
    for (int nt = 0; nt < 8; nt++) {           // K
        const int head = nt >> 1;
        const int kk0  = (nt & 1) * 8 + 2 * gc;
        const size_t base = (size_t)(b * 4 + head) * 2048;
        *(__half2*)&g_Kh[(base + sb + gr)     * 16 + kk0] = __floats2half2_rn(acc[8 + nt][0], acc[8 + nt][1]);
        *(__half2*)&g_Kh[(base + sb + gr + 8) * 16 + kk0] = __floats2half2_rn(acc[8 + nt][2], acc[8 + nt][3]);
    }

    const int s0 = (blockIdx.x * 64) & 2047;
    const int bb = (blockIdx.x * 64) >> 11;
#pragma unroll
    for (int q = 0; q < 4; q++) {
        const int idx = q * 128 + tid;
        const int c   = idx >> 3;
        const int j   = idx & 7;
        const int h   = c >> 4;
        const int kk  = c & 15;
        __half2 p0 = __halves2half2(stage_v[(8*j+0)*66+c], stage_v[(8*j+1)*66+c]);
        __half2 p1 = __halves2half2(stage_v[(8*j+2)*66+c], stage_v[(8*j+3)*66+c]);
        __half2 p2 = __halves2half2(stage_v[(8*j+4)*66+c], stage_v[(8*j+5)*66+c]);
        __half2 p3 = __halves2half2(stage_v[(8*j+6)*66+c], stage_v[(8*j+7)*66+c]);
        uint4 u;
        u.x = *(unsigned*)&p0; u.y = *(unsigned*)&p1;
        u.z = *(unsigned*)&p2; u.w = *(unsigned*)&p3;
        *(uint4*)&g_Vt[((size_t)(bb * 4 + h) * 16 + kk) * 2048 + s0 + 8 * j] = u;
    }
}

// =====================================================================
// Kernel 2: split-K flash attention. Block = (bh, q-slab 128, kv-split).
// 8 chunks per block; l accumulated from P regs (hadd2) on FMA pipe —
// no ones-column MMA. Writes UNNORMALIZED partial O and quad-reduced l.
// =====================================================================
__global__ void __launch_bounds__(128) attn_kernel()
{
    __shared__ __align__(16) __half Ksh[2][BK][24];   // stride 24 halves
    __shared__ __align__(16) __half Vts[2][16][72];   // [dim][key]

    const int bh    = blockIdx.x;
    const int split = blockIdx.z;
    const int tid   = threadIdx.x;
    const int warp  = tid >> 5;
    const int lane  = tid & 31;
    const int gr    = lane >> 2;
    const int gc    = lane & 3;
    const int qrow0 = blockIdx.y * 128 + warp * 32;
    const int c0    = split * CPS;

    // Q fragments (held for whole kernel)
    const __half* Qbh = g_Qh + (size_t)bh * SS * HEADD;
    unsigned qa[2][4];
#pragma unroll
    for (int mt = 0; mt < 2; mt++) {
        const __half* r0 = Qbh + (size_t)(qrow0 + mt * 16 + gr) * HEADD;
        qa[mt][0] = *(const unsigned*)(r0 + 2 * gc);
        qa[mt][1] = *(const unsigned*)(r0 + 8 * HEADD + 2 * gc);
        qa[mt][2] = *(const unsigned*)(r0 + 2 * gc + 8);
        qa[mt][3] = *(const unsigned*)(r0 + 8 * HEADD + 2 * gc + 8);
    }

    const __half* Kbh = g_Kh + (size_t)bh * SS * HEADD;
    const __half* Vbh = g_Vt + (size_t)bh * HEADD * SS;

    const int kr = tid >> 1, ko = (tid & 1) * 8;   // K: row, half-offset
    const int vd = tid >> 3, vo = (tid & 7) * 8;   // V: dim (0..15), key-offset

    float4 nk = *(const float4*)(Kbh + (size_t)(c0 * BK + kr) * HEADD + ko);
    float4 nv = *(const float4*)(Vbh + (size_t)vd * SS + c0 * BK + vo);
    *(float4*)&Ksh[0][kr][ko] = nk;
    *(float4*)&Vts[0][vd][vo] = nv;
    __syncthreads();

    float O[2][2][4] = {};      // [mt][nv-tile][frag]
    float lacc[2][2] = {};      // [mt][row-half]
    unsigned P[2][8][2];

    for (int cc = 0; cc < CPS; cc++) {
        const int c   = c0 + cc;
        const int buf = cc & 1;
        if (cc + 1 < CPS) {
            nk = *(const float4*)(Kbh + (size_t)((c + 1) * BK + kr) * HEADD + ko);
            nv = *(const float4*)(Vbh + (size_t)vd * SS + (c + 1) * BK + vo);
        }

        // ---- S = Q @ K^T, then P = exp2(S) packed fp16 ----
#pragma unroll
        for (int nt = 0; nt < 8; nt++) {
            unsigned b0 = *(const unsigned*)&Ksh[buf][nt * 8 + gr][2 * gc];
            unsigned b1 = *(const unsigned*)&Ksh[buf][nt * 8 + gr][2 * gc + 8];
            float s[4] = {0.f, 0.f, 0.f, 0.f};
            float t[4] = {0.f, 0.f, 0.f, 0.f};
            mma_16816(s, qa[0], b0, b1);
            mma_16816(t, qa[1], b0, b1);
            P[0][nt][0] = h2exp2_fast(packh2(s[0], s[1]));
            P[0][nt][1] = h2exp2_fast(packh2(s[2], s[3]));
            P[1][nt][0] = h2exp2_fast(packh2(t[0], t[1]));
            P[1][nt][1] = h2exp2_fast(packh2(t[2], t[3]));
        }

        // ---- l accumulation on FMA/ALU pipes ----
#pragma unroll
        for (int mt = 0; mt < 2; mt++) {
            __half2 s0 = *(__half2*)&P[mt][0][0];
            __half2 s1 = *(__half2*)&P[mt][0][1];
#pragma unroll
            for (int nt = 1; nt < 8; nt++) {
                s0 = __hadd2(s0, *(__half2*)&P[mt][nt][0]);
                s1 = __hadd2(s1, *(__half2*)&P[mt][nt][1]);
            }
            float2 f0 = __half22float2(s0);
            float2 f1 = __half22float2(s1);
            lacc[mt][0] += f0.x + f0.y;
            lacc[mt][1] += f1.x + f1.y;
        }

        // ---- O += P @ Vt ----
#pragma unroll
        for (int kt = 0; kt < 4; kt++) {
            unsigned a0[4] = { P[0][2*kt][0], P[0][2*kt][1],
                               P[0][2*kt+1][0], P[0][2*kt+1][1] };
            unsigned a1[4] = { P[1][2*kt][0], P[1][2*kt][1],
                               P[1][2*kt+1][0], P[1][2*kt+1][1] };
#pragma unroll
            for (int nvt = 0; nvt < 2; nvt++) {
                unsigned b0 = *(const unsigned*)&Vts[buf][nvt * 8 + gr][kt * 16 + 2 * gc];
                unsigned b1 = *(const unsigned*)&Vts[buf][nvt * 8 + gr][kt * 16 + 2 * gc + 8];
                mma_16816(O[0][nvt], a0, b0, b1);
                mma_16816(O[1][nvt], a1, b0, b1);
            }
        }

        __syncthreads();
        if (cc + 1 < CPS) {
            *(float4*)&Ksh[buf ^ 1][kr][ko] = nk;
            *(float4*)&Vts[buf ^ 1][vd][vo] = nv;
        }
        __syncthreads();
    }

    // ---- epilogue: store UNNORMALIZED partial O and quad-reduced l ----
    const size_t rowbase = (size_t)split * NROWS + (size_t)bh * SS;
#pragma unroll
    for (int mt = 0; mt < 2; mt++) {
        float l_lo = lacc[mt][0];
        float l_hi = lacc[mt][1];
        l_lo += __shfl_xor_sync(0xffffffffu, l_lo, 1);
        l_lo += __shfl_xor_sync(0xffffffffu, l_lo, 2);
        l_hi += __shfl_xor_sync(0xffffffffu, l_hi, 1);
        l_hi += __shfl_xor_sync(0xffffffffu, l_hi, 2);
        const int r_lo = qrow0 + mt * 16 + gr;
        const int r_hi = r_lo + 8;
#pragma unroll
        for (int nvt = 0; nvt < 2; nvt++) {
            *(float2*)&g_Opart[(rowbase + r_lo) * HEADD + nvt * 8 + 2 * gc] =
                make_float2(O[mt][nvt][0], O[mt][nvt][1]);
            *(float2*)&g_Opart[(rowbase + r_hi) * HEADD + nvt * 8 + 2 * gc] =
                make_float2(O[mt][nvt][2], O[mt][nvt][3]);
        }
        if (gc == 0) {
            g_lpart[rowbase + r_lo] = l_lo;
            g_lpart[rowbase + r_hi] = l_hi;
        }
    }
}

// =====================================================================
// Kernel 3: post block on tensor cores, with FUSED split reduction.
// A-fragments built by summing NSPLIT partials + l and normalizing
// (head index == k-tile index, so the gather is layout-natural).
// =====================================================================
__global__ void __launch_bounds__(128) post_kernel(
    const float* __restrict__ data,
    const float* __restrict__ bo,
    const float* __restrict__ g1,  const float* __restrict__ bl1,
    const float* __restrict__ b1,  const float* __restrict__ b2,
    const float* __restrict__ g2,  const float* __restrict__ bl2,
    float* __restrict__ out)
{
    const int tid  = threadIdx.x;
    const int warp = tid >> 5;
    const int lane = tid & 31;
    const int gr   = lane >> 2;
    const int gc   = lane & 3;

    const int tile = blockIdx.x * 4 + warp;
    const int tok0 = tile * 16;
    const int b    = tok0 >> 11;
    const int sb   = tok0 & 2047;
    const float* rowL = data + (size_t)(tok0 + gr) * 64;
    const float* rowH = rowL + 8 * 64;

    // ---- fused reduce: A fragments from split partials (head = kt) ----
    unsigned a[4][4];
#pragma unroll
    for (int kt = 0; kt < 4; kt++) {
        const size_t row_lo = (size_t)(b * 4 + kt) * 2048 + sb + gr;
        const size_t row_hi = row_lo + 8;
        float l_lo = 0.f, l_hi = 0.f;
        float2 oL0 = {0.f,0.f}, oL8 = {0.f,0.f}, oH0 = {0.f,0.f}, oH8 = {0.f,0.f};
#pragma unroll
        for (int sp = 0; sp < NSPLIT; sp++) {
            const float* OL = &g_Opart[((size_t)sp * NROWS + row_lo) * HEADD];
            const float* OH = &g_Opart[((size_t)sp * NROWS + row_hi) * HEADD];
            float2 t;
            t = *(const float2*)(OL + 2 * gc);     oL0.x += t.x; oL0.y += t.y;
            t = *(const float2*)(OL + 8 + 2 * gc); oL8.x += t.x; oL8.y += t.y;
            t = *(const float2*)(OH + 2 * gc);     oH0.x += t.x; oH0.y += t.y;
            t = *(const float2*)(OH + 8 + 2 * gc); oH8.x += t.x; oH8.y += t.y;
            l_lo += g_lpart[(size_t)sp * NROWS + row_lo];
            l_hi += g_lpart[(size_t)sp * NROWS + row_hi];
        }
        const float invL = 1.f / l_lo, invH = 1.f / l_hi;
        a[kt][0] = packh2(oL0.x * invL, oL0.y * invL);
        a[kt][1] = packh2(oH0.x * invH, oH0.y * invH);
        a[kt][2] = packh2(oL8.x * invL, oL8.y * invL);
        a[kt][3] = packh2(oH8.x * invH, oH8.y * invH);
    }

    // ---- GEMM1: heads @ Wo ----
    float acc[8][4] = {};
#pragma unroll
    for (int nt = 0; nt < 8; nt++)
#pragma unroll
        for (int kt = 0; kt < 4; kt++) {
            const __half* base = &g_Wpost[(nt * 8 + gr) * 72 + kt * 16 + 2 * gc];
            mma_16816(acc[nt], a[kt], *(const unsigned*)base, *(const unsigned*)(base + 8));
        }

    float x1[8][4];
    float sl = 0.f, sh = 0.f;
#pragma unroll
    for (int nt = 0; nt < 8; nt++) {
        const int col = nt * 8 + 2 * gc;
        float2 dl = *(const float2*)(rowL + col);
        float2 dh = *(const float2*)(rowH + col);
        float2 bb = *(const float2*)(bo + col);
        x1[nt][0] = acc[nt][0] + dl.x + bb.x;
        x1[nt][1] = acc[nt][1] + dl.y + bb.y;
        x1[nt][2] = acc[nt][2] + dh.x + bb.x;
        x1[nt][3] = acc[nt][3] + dh.y + bb.y;
        sl += x1[nt][0] + x1[nt][1];
        sh += x1[nt][2] + x1[nt][3];
    }
    sl += __shfl_xor_sync(0xffffffffu, sl, 1); sl += __shfl_xor_sync(0xffffffffu, sl, 2);
    sh += __shfl_xor_sync(0xffffffffu, sh, 1); sh += __shfl_xor_sync(0xffffffffu, sh, 2);
    float ml = sl * (1.f / 64.f), mh = sh * (1.f / 64.f);
    float vl = 0.f, vh = 0.f;
#pragma unroll
    for (int nt = 0; nt < 8; nt++) {
        x1[nt][0] -= ml; x1[nt][1] -= ml; x1[nt][2] -= mh; x1[nt][3] -= mh;
        vl += x1[nt][0]*x1[nt][0] + x1[nt][1]*x1[nt][1];
        vh += x1[nt][2]*x1[nt][2] + x1[nt][3]*x1[nt][3];
    }
    vl += __shfl_xor_sync(0xffffffffu, vl, 1); vl += __shfl_xor_sync(0xffffffffu, vl, 2);
    vh += __shfl_xor_sync(0xffffffffu, vh, 1); vh += __shfl_xor_sync(0xffffffffu, vh, 2);
    float il = rsqrtf(vl * (1.f / 64.f) + EPS);
    float ih = rsqrtf(vh * (1.f / 64.f) + EPS);
#pragma unroll
    for (int nt = 0; nt < 8; nt++) {
        const int col = nt * 8 + 2 * gc;
        float2 gg = *(const float2*)(g1 + col);
        float2 ee = *(const float2*)(bl1 + col);
        x1[nt][0] = x1[nt][0] * il * gg.x + ee.x;
        x1[nt][1] = x1[nt][1] * il * gg.y + ee.y;
        x1[nt][2] = x1[nt][2] * ih * gg.x + ee.x;
        x1[nt][3] = x1[nt][3] * ih * gg.y + ee.y;
    }

#pragma unroll
    for (int kt = 0; kt < 4; kt++) {
        a[kt][0] = packh2(x1[2*kt][0],   x1[2*kt][1]);
        a[kt][1] = packh2(x1[2*kt][2],   x1[2*kt][3]);
        a[kt][2] = packh2(x1[2*kt+1][0], x1[2*kt+1][1]);
        a[kt][3] = packh2(x1[2*kt+1][2], x1[2*kt+1][3]);
    }
    float acc2[8][4] = {};
#pragma unroll
    for (int nt = 0; nt < 8; nt++)
#pragma unroll
        for (int kt = 0; kt < 4; kt++) {
            const __half* base = &g_Wpost[(64 + nt * 8 + gr) * 72 + kt * 16 + 2 * gc];
            mma_16816(acc2[nt], a[kt], *(const unsigned*)base, *(const unsigned*)(base + 8));
        }

#pragma unroll
    for (int nt = 0; nt < 8; nt++) {
        const int col = nt * 8 + 2 * gc;
        float2 bb = *(const float2*)(b1 + col);
        acc2[nt][0] = fmaxf(acc2[nt][0] + bb.x, 0.f);
        acc2[nt][1] = fmaxf(acc2[nt][1] + bb.y, 0.f);
        acc2[nt][2] = fmaxf(acc2[nt][2] + bb.x, 0.f);
        acc2[nt][3] = fmaxf(acc2[nt][3] + bb.y, 0.f);
    }
#pragma unroll
    for (int kt = 0; kt < 4; kt++) {
        a[kt][0] = packh2(acc2[2*kt][0],   acc2[2*kt][1]);
        a[kt][1] = packh2(acc2[2*kt][2],   acc2[2*kt][3]);
        a[kt][2] = packh2(acc2[2*kt+1][0], acc2[2*kt+1][1]);
        a[kt][3] = packh2(acc2[2*kt+1][2], acc2[2*kt+1][3]);
    }

    float acc3[8][4] = {};
#pragma unroll
    for (int nt = 0; nt < 8; nt++)
#pragma unroll
        for (int kt = 0; kt < 4; kt++) {
            const __half* base = &g_Wpost[(128 + nt * 8 + gr) * 72 + kt * 16 + 2 * gc];
            mma_16816(acc3[nt], a[kt], *(const unsigned*)base, *(const unsigned*)(base + 8));
        }

    sl = 0.f; sh = 0.f;
#pragma unroll
    for (int nt = 0; nt < 8; nt++) {
        const int col = nt * 8 + 2 * gc;
        float2 bb = *(const float2*)(b2 + col);
        acc3[nt][0] += bb.x + x1[nt][0];
        acc3[nt][1] += bb.y + x1[nt][1];
        acc3[nt][2] += bb.x + x1[nt][2];
        acc3[nt][3] += bb.y + x1[nt][3];
        sl += acc3[nt][0] + acc3[nt][1];
        sh += acc3[nt][2] + acc3[nt][3];
    }
    sl += __shfl_xor_sync(0xffffffffu, sl, 1); sl += __shfl_xor_sync(0xffffffffu, sl, 2);
    sh += __shfl_xor_sync(0xffffffffu, sh, 1); sh += __shfl_xor_sync(0xffffffffu, sh, 2);
    ml = sl * (1.f / 64.f); mh = sh * (1.f / 64.f);
    vl = 0.f; vh = 0.f;
#pragma unroll
    for (int nt = 0; nt < 8; nt++) {
        acc3[nt][0] -= ml; acc3[nt][1] -= ml; acc3[nt][2] -= mh; acc3[nt][3] -= mh;
        vl += acc3[nt][0]*acc3[nt][0] + acc3[nt][1]*acc3[nt][1];
        vh += acc3[nt][2]*acc3[nt][2] + acc3[nt][3]*acc3[nt][3];
    }
    vl += __shfl_xor_sync(0xffffffffu, vl, 1); vl += __shfl_xor_sync(0xffffffffu, vl, 2);
    vh += __shfl_xor_sync(0xffffffffu, vh, 1); vh += __shfl_xor_sync(0xffffffffu, vh, 2);
    il = rsqrtf(vl * (1.f / 64.f) + EPS);
    ih = rsqrtf(vh * (1.f / 64.f) + EPS);

    float* outL = out + (size_t)(tok0 + gr) * 64;
    float* outH = outL + 8 * 64;
#pragma unroll
    for (int nt = 0; nt < 8; nt++) {
        const int col = nt * 8 + 2 * gc;
        float2 gg = *(const float2*)(g2 + col);
        float2 ee = *(const float2*)(bl2 + col);
        *(float2*)(outL + col) = make_float2(acc3[nt][0] * il * gg.x + ee.x,
                                             acc3[nt][1] * il * gg.y + ee.y);
        *(float2*)(outH + col) = make_float2(acc3[nt][2] * ih * gg.x + ee.x,
                                             acc3[nt][3] * ih * gg.y + ee.y);
    }
}

// =====================================================================
extern "C" void kernel_launch(void* const* d_in, const int* in_sizes, int n_in,
                              void* d_out, int out_size)
{
    const float* data  = (const float*)d_in[0];
    const float* Wq    = (const float*)d_in[1];
    const float* Wk    = (const float*)d_in[2];
    const float* Wv    = (const float*)d_in[3];
    const float* Wo    = (const float*)d_in[4];
    const float* bo    = (const float*)d_in[5];
    const float* ln1_g = (const float*)d_in[6];
    const float* ln1_b = (const float*)d_in[7];
    const float* W1    = (const float*)d_in[8];
    const float* b1    = (const float*)d_in[9];
    const float* W2    = (const float*)d_in[10];
    const float* b2    = (const float*)d_in[11];
    const float* ln2_g = (const float*)d_in[12];
    const float* ln2_b = (const float*)d_in[13];
    float* out = (float*)d_out;

    prep_kernel<<<96, 256>>>(Wq, Wk, Wv, Wo, W1, W2);
    qkv_kernel<<<256, 128>>>(data);
    attn_kernel<<<dim3(NHEAD * BB, SS / 128, NSPLIT), 128>>>();
    post_kernel<<<256, 128>>>(data, bo, ln1_g, ln1_b, b1, b2, ln2_g, ln2_b, out);
}